// round 1
// baseline (speedup 1.0000x reference)
#include <cuda_runtime.h>
#include <cstdint>

// ---------------------------------------------------------------------------
// PatternBasedV2_260: pattern-hash EmbeddingBag(max_norm=1) + 3-layer MLP
// Inputs (metadata order):
//   0: x    int32  [8192, 2, 8, 8]
//   1: emb  f32    [225990, 256]
//   2: w1   f32    [256, 64]
//   3: b1   f32    [64]
//   4: w2   f32    [64, 32]
//   5: b2   f32    [32]
//   6: w3   f32    [32, 1]
//   7: b3   f32    [1]
// Output: f32 [8192, 1]
// ---------------------------------------------------------------------------

#define NUM_PATTERNS 16
#define FRONT 256
#define MID 64
#define BACK 32

// Lookup tables built on-device each launch (deterministic, capturable).
__device__ int d_patpos[NUM_PATTERNS][16]; // bit positions (ascending) per pattern
__device__ int d_patlen[NUM_PATTERNS];
__device__ int d_bias[NUM_PATTERNS];       // cumulative offset into emb table
__device__ int d_tpos[8][64];              // symmetry k, cell pos -> original cell

__global__ void init_tables_kernel() {
    if (threadIdx.x != 0 || blockIdx.x != 0) return;
    const unsigned long long P[NUM_PATTERNS] = {
        16639ULL, 65280ULL, 16711680ULL, 4278190080ULL, 3871ULL, 198415ULL,
        4345695256ULL, 1108169199648ULL, 283691315109952ULL,
        72624976668147840ULL, 7357ULL, 135137027ULL, 460551ULL, 1279ULL,
        134614787ULL, 33693443ULL};
    int off = 0;
    for (int p = 0; p < NUM_PATTERNS; p++) {
        int len = 0;
        for (int i = 0; i < 64; i++)
            if ((P[p] >> i) & 1ULL) d_patpos[p][len++] = i;
        d_patlen[p] = len;
        d_bias[p] = off;
        int t = 1;
        for (int j = 0; j < len; j++) t *= 3;
        off += t;
    }
    // symmetry k = 4*colflip + 2*rowflip + transpose
    // board_k[R][C] = v[R2][C2] (or transposed), with
    //   C2 = colflip ? 7-C : C ; R2 = rowflip ? 7-R : R
    for (int k = 0; k < 8; k++) {
        for (int pos = 0; pos < 64; pos++) {
            int R = pos >> 3, C = pos & 7;
            int C2 = (k & 4) ? 7 - C : C;
            int R2 = (k & 2) ? 7 - R : R;
            d_tpos[k][pos] = (k & 1) ? (C2 * 8 + R2) : (R2 * 8 + C2);
        }
    }
}

__global__ __launch_bounds__(256) void pattern_forward_kernel(
    const int* __restrict__ x, const float* __restrict__ emb,
    const float* __restrict__ w1, const float* __restrict__ b1,
    const float* __restrict__ w2, const float* __restrict__ b2,
    const float* __restrict__ w3, const float* __restrict__ b3,
    float* __restrict__ out)
{
    __shared__ int v[64];
    __shared__ int sidx[128];
    __shared__ float wacc[8][FRONT];
    __shared__ float m[FRONT];
    __shared__ float h1[MID];
    __shared__ float h2[BACK];

    const int b = blockIdx.x;
    const int t = threadIdx.x;
    const int warp = t >> 5, lane = t & 31;

    // 1) board cells: v = plane0 + 2*plane1  (values in {0,1,2})
    const int* xb = x + (size_t)b * 128;
    if (t < 64) v[t] = xb[t] + 2 * xb[64 + t];
    __syncthreads();

    // 2) 128 pattern indices (8 symmetries x 16 patterns)
    if (t < 128) {
        const int k = t >> 4, p = t & 15;
        const int len = d_patlen[p];
        int s = d_bias[p];
        int w = 1;
        #pragma unroll 4
        for (int i = 0; i < len; i++) {
            s += w * v[d_tpos[k][d_patpos[p][i]]];
            w *= 3;
        }
        sidx[t] = s;
    }
    __syncthreads();

    // 3) gather + conditional renorm + sum. Warp w handles rows [16w, 16w+16).
    //    Each lane covers dims [4*lane,4*lane+4) and [128+4*lane, ...+4).
    const float4* __restrict__ embv = (const float4*)emb;
    float4 acc0 = make_float4(0.f, 0.f, 0.f, 0.f);
    float4 acc1 = make_float4(0.f, 0.f, 0.f, 0.f);
    const int base = warp * 16;

    int row = sidx[base] * 64;  // fits int: 225990*64 < 2^31
    float4 a = embv[row + lane];
    float4 c = embv[row + 32 + lane];
    #pragma unroll
    for (int i = 0; i < 16; i++) {
        float4 na, nc;
        if (i < 15) {  // prefetch next row
            int nr = sidx[base + i + 1] * 64;
            na = embv[nr + lane];
            nc = embv[nr + 32 + lane];
        }
        float ss = a.x * a.x + a.y * a.y + a.z * a.z + a.w * a.w
                 + c.x * c.x + c.y * c.y + c.z * c.z + c.w * c.w;
        #pragma unroll
        for (int o = 16; o > 0; o >>= 1)
            ss += __shfl_xor_sync(0xffffffffu, ss, o);
        float scale = 1.0f;
        if (ss > 1.0f) scale = 1.0f / (sqrtf(ss) + 1e-7f);
        acc0.x += scale * a.x; acc0.y += scale * a.y;
        acc0.z += scale * a.z; acc0.w += scale * a.w;
        acc1.x += scale * c.x; acc1.y += scale * c.y;
        acc1.z += scale * c.z; acc1.w += scale * c.w;
        a = na; c = nc;
    }
    {
        float* wa = wacc[warp];
        wa[lane * 4 + 0] = acc0.x; wa[lane * 4 + 1] = acc0.y;
        wa[lane * 4 + 2] = acc0.z; wa[lane * 4 + 3] = acc0.w;
        wa[128 + lane * 4 + 0] = acc1.x; wa[128 + lane * 4 + 1] = acc1.y;
        wa[128 + lane * 4 + 2] = acc1.z; wa[128 + lane * 4 + 3] = acc1.w;
    }
    __syncthreads();

    // 4) reduce the 8 warp partials -> m[256]
    {
        float s = 0.f;
        #pragma unroll
        for (int wg = 0; wg < 8; wg++) s += wacc[wg][t];
        m[t] = s;
    }
    __syncthreads();

    // 5) MLP: 256 -> 64 (relu) -> 32 (relu) -> 1
    if (t < MID) {
        float acc = b1[t];
        #pragma unroll 8
        for (int i = 0; i < FRONT; i++) acc = fmaf(m[i], w1[i * MID + t], acc);
        h1[t] = fmaxf(acc, 0.f);
    }
    __syncthreads();
    if (t < BACK) {
        float acc = b2[t];
        #pragma unroll 8
        for (int i = 0; i < MID; i++) acc = fmaf(h1[i], w2[i * BACK + t], acc);
        h2[t] = fmaxf(acc, 0.f);
    }
    __syncthreads();
    if (t == 0) {
        float acc = b3[0];
        #pragma unroll
        for (int i = 0; i < BACK; i++) acc = fmaf(h2[i], w3[i], acc);
        out[b] = acc;
    }
}

extern "C" void kernel_launch(void* const* d_in, const int* in_sizes, int n_in,
                              void* d_out, int out_size)
{
    const int* x = (const int*)d_in[0];
    const float* emb = (const float*)d_in[1];
    const float* w1 = (const float*)d_in[2];
    const float* b1 = (const float*)d_in[3];
    const float* w2 = (const float*)d_in[4];
    const float* b2 = (const float*)d_in[5];
    const float* w3 = (const float*)d_in[6];
    const float* b3 = (const float*)d_in[7];
    float* out = (float*)d_out;

    const int batch = in_sizes[0] / 128;  // [B,2,8,8] int32

    init_tables_kernel<<<1, 32>>>();
    pattern_forward_kernel<<<batch, 256>>>(x, emb, w1, b1, w2, b2, w3, b3, out);
}